// round 1
// baseline (speedup 1.0000x reference)
#include <cuda_runtime.h>
#include <math.h>

#define BB 2
#define SS 2048
#define DD 1024
#define HH 16
#define DKK 64

// Scratch (allocation-free rule: __device__ globals)
__device__ float g_qp[BB * SS * DD];
__device__ float g_kp[BB * SS * DD];
__device__ float g_vp[BB * SS * DD];
__device__ float g_at[BB * SS * DD];

// ---------------------------------------------------------------------------
// SGEMM with bias: C[M,N] = A[M,K] @ W[K,N] + bias[N]
// BM=BN=128, BK=8, 256 threads, 8x8 microtile per thread.
// ---------------------------------------------------------------------------
__global__ __launch_bounds__(256) void gemm_bias_kernel(
    const float* __restrict__ A, const float* __restrict__ W,
    const float* __restrict__ bias, float* __restrict__ C,
    int M, int N, int K)
{
    __shared__ float As[8][132];
    __shared__ float Bs[8][132];

    const int tid = threadIdx.x;
    const int bm = blockIdx.y * 128;
    const int bn = blockIdx.x * 128;

    const int arow = tid >> 1;          // 0..127
    const int acol = (tid & 1) << 2;    // 0 or 4
    const int brow = tid >> 5;          // 0..7
    const int bcol = (tid & 31) << 2;   // 0..124

    const int tx = tid & 15;
    const int ty = tid >> 4;

    float acc[8][8];
#pragma unroll
    for (int i = 0; i < 8; i++)
#pragma unroll
        for (int j = 0; j < 8; j++) acc[i][j] = 0.f;

    const float* Ap = A + (size_t)(bm + arow) * K + acol;
    const float* Wp = W + (size_t)brow * N + bn + bcol;

    for (int k0 = 0; k0 < K; k0 += 8) {
        float4 a4 = *(const float4*)(Ap + k0);
        float4 b4 = *(const float4*)(Wp + (size_t)k0 * N);
        As[acol + 0][arow] = a4.x;
        As[acol + 1][arow] = a4.y;
        As[acol + 2][arow] = a4.z;
        As[acol + 3][arow] = a4.w;
        *(float4*)&Bs[brow][bcol] = b4;
        __syncthreads();
#pragma unroll
        for (int kk = 0; kk < 8; kk++) {
            float am[8], wn[8];
            *(float4*)&am[0] = *(float4*)&As[kk][ty * 8];
            *(float4*)&am[4] = *(float4*)&As[kk][ty * 8 + 4];
            *(float4*)&wn[0] = *(float4*)&Bs[kk][tx * 8];
            *(float4*)&wn[4] = *(float4*)&Bs[kk][tx * 8 + 4];
#pragma unroll
            for (int i = 0; i < 8; i++)
#pragma unroll
                for (int j = 0; j < 8; j++)
                    acc[i][j] += am[i] * wn[j];
        }
        __syncthreads();
    }

    float bb[8];
#pragma unroll
    for (int j = 0; j < 8; j++) bb[j] = bias[bn + tx * 8 + j];

#pragma unroll
    for (int i = 0; i < 8; i++) {
        float* Cp = C + (size_t)(bm + ty * 8 + i) * N + bn + tx * 8;
        float4 o0 = make_float4(acc[i][0] + bb[0], acc[i][1] + bb[1],
                                acc[i][2] + bb[2], acc[i][3] + bb[3]);
        float4 o1 = make_float4(acc[i][4] + bb[4], acc[i][5] + bb[5],
                                acc[i][6] + bb[6], acc[i][7] + bb[7]);
        *(float4*)(Cp)     = o0;
        *(float4*)(Cp + 4) = o1;
    }
}

// ---------------------------------------------------------------------------
// Flash attention: one block = (batch b, head h, 64-row q-tile).
// smem tiles 64x64 (pad 65). Online softmax. Mask: mask[b,k] != 0 => -1e10.
// Thread (tx,ty) owns rows {ty+16i} and cols {tx+16j}, i,j in 0..3.
// ---------------------------------------------------------------------------
#define TP 65  // smem row pitch

__global__ __launch_bounds__(256) void attn_kernel(
    const float* __restrict__ Qm, const float* __restrict__ Km,
    const float* __restrict__ Vm, const int* __restrict__ mask,
    float* __restrict__ Om)
{
    extern __shared__ float smem[];
    float* sQ  = smem;                  // 64*65
    float* sKV = sQ + 64 * TP;          // 64*65  (K, then reused for V)
    float* sS  = sKV + 64 * TP;         // 64*65
    float* sM  = sS + 64 * TP;          // 64
    float* sL  = sM + 64;               // 64
    float* sC  = sL + 64;               // 64
    float* sMk = sC + 64;               // 64 (mask flags as float)

    const int tid = threadIdx.x;
    const int tx = tid & 15;
    const int ty = tid >> 4;
    const int b = blockIdx.y >> 4;      // / HH
    const int h = blockIdx.y & 15;      // % HH
    const int q0 = blockIdx.x << 6;

    const size_t headoff = (size_t)h * DKK;
    const float* Qb = Qm + ((size_t)b * SS + q0) * DD + headoff;
    const float* Kb = Km + (size_t)b * SS * DD + headoff;
    const float* Vb = Vm + (size_t)b * SS * DD + headoff;
    const int* mb = mask + b * SS;

    // Load Q tile (64x64), pre-scaled by 1/sqrt(DK) = 0.125
#pragma unroll
    for (int p = 0; p < 4; p++) {
        int L = tid + p * 256;
        int r = L >> 4;
        int c = (L & 15) << 2;
        float4 v = *(const float4*)(Qb + (size_t)r * DD + c);
        sQ[r * TP + c + 0] = v.x * 0.125f;
        sQ[r * TP + c + 1] = v.y * 0.125f;
        sQ[r * TP + c + 2] = v.z * 0.125f;
        sQ[r * TP + c + 3] = v.w * 0.125f;
    }
    if (tid < 64) { sM[tid] = -3.0e38f; sL[tid] = 0.f; }

    float acc[4][4];
#pragma unroll
    for (int i = 0; i < 4; i++)
#pragma unroll
        for (int j = 0; j < 4; j++) acc[i][j] = 0.f;

    for (int kt = 0; kt < SS / 64; kt++) {
        const float* Kt = Kb + (size_t)kt * 64 * DD;
        const float* Vt = Vb + (size_t)kt * 64 * DD;

        // Load K tile
#pragma unroll
        for (int p = 0; p < 4; p++) {
            int L = tid + p * 256;
            int r = L >> 4;
            int c = (L & 15) << 2;
            float4 v = *(const float4*)(Kt + (size_t)r * DD + c);
            sKV[r * TP + c + 0] = v.x;
            sKV[r * TP + c + 1] = v.y;
            sKV[r * TP + c + 2] = v.z;
            sKV[r * TP + c + 3] = v.w;
        }
        if (tid < 64) sMk[tid] = (mb[kt * 64 + tid] != 0) ? 1.f : 0.f;
        __syncthreads();

        // S = Q @ K^T  (4x4 per thread)
        float s[4][4];
#pragma unroll
        for (int i = 0; i < 4; i++)
#pragma unroll
            for (int j = 0; j < 4; j++) s[i][j] = 0.f;
#pragma unroll
        for (int d = 0; d < 64; d++) {
            float qv[4], kv[4];
#pragma unroll
            for (int i = 0; i < 4; i++) qv[i] = sQ[(ty + 16 * i) * TP + d];
#pragma unroll
            for (int j = 0; j < 4; j++) kv[j] = sKV[(tx + 16 * j) * TP + d];
#pragma unroll
            for (int i = 0; i < 4; i++)
#pragma unroll
                for (int j = 0; j < 4; j++)
                    s[i][j] += qv[i] * kv[j];
        }
#pragma unroll
        for (int i = 0; i < 4; i++)
#pragma unroll
            for (int j = 0; j < 4; j++)
                sS[(ty + 16 * i) * TP + tx + 16 * j] = s[i][j];
        __syncthreads();   // K reads done; S tile complete

        // Load V tile into sKV (everyone), then 64 threads do softmax on sS
#pragma unroll
        for (int p = 0; p < 4; p++) {
            int L = tid + p * 256;
            int r = L >> 4;
            int c = (L & 15) << 2;
            float4 v = *(const float4*)(Vt + (size_t)r * DD + c);
            sKV[r * TP + c + 0] = v.x;
            sKV[r * TP + c + 1] = v.y;
            sKV[r * TP + c + 2] = v.z;
            sKV[r * TP + c + 3] = v.w;
        }

        if (tid < 64) {
            const int r = tid;
            float mOld = sM[r];
            float mt = mOld;
#pragma unroll 8
            for (int j = 0; j < 64; j++) {
                float sv = (sMk[j] != 0.f) ? -1.0e10f : sS[r * TP + j];
                sS[r * TP + j] = sv;
                mt = fmaxf(mt, sv);
            }
            float corr = __expf(mOld - mt);
            float l = sL[r] * corr;
#pragma unroll 8
            for (int j = 0; j < 64; j++) {
                float p = __expf(sS[r * TP + j] - mt);
                sS[r * TP + j] = p;
                l += p;
            }
            sL[r] = l;
            sM[r] = mt;
            sC[r] = corr;
        }
        __syncthreads();

        // Rescale accumulators, then O += P @ V
        float cf[4];
#pragma unroll
        for (int i = 0; i < 4; i++) cf[i] = sC[ty + 16 * i];
#pragma unroll
        for (int i = 0; i < 4; i++)
#pragma unroll
            for (int j = 0; j < 4; j++) acc[i][j] *= cf[i];

#pragma unroll
        for (int k = 0; k < 64; k++) {
            float pv[4], vv[4];
#pragma unroll
            for (int i = 0; i < 4; i++) pv[i] = sS[(ty + 16 * i) * TP + k];
#pragma unroll
            for (int j = 0; j < 4; j++) vv[j] = sKV[k * TP + tx + 16 * j];
#pragma unroll
            for (int i = 0; i < 4; i++)
#pragma unroll
                for (int j = 0; j < 4; j++)
                    acc[i][j] += pv[i] * vv[j];
        }
        __syncthreads();
    }

    // Final normalize + store: O[b, q0+r, h*64 + c]
#pragma unroll
    for (int i = 0; i < 4; i++) {
        int r = ty + 16 * i;
        float inv = 1.f / sL[r];
        float* Op = Om + ((size_t)b * SS + q0 + r) * DD + headoff;
#pragma unroll
        for (int j = 0; j < 4; j++)
            Op[tx + 16 * j] = acc[i][j] * inv;
    }
}

// ---------------------------------------------------------------------------
extern "C" void kernel_launch(void* const* d_in, const int* in_sizes, int n_in,
                              void* d_out, int out_size)
{
    const float* q    = (const float*)d_in[0];
    const float* k    = (const float*)d_in[1];
    const float* v    = (const float*)d_in[2];
    const int*   mask = (const int*)d_in[3];
    const float* Wq   = (const float*)d_in[4];
    const float* bq   = (const float*)d_in[5];
    const float* Wk   = (const float*)d_in[6];
    const float* bk   = (const float*)d_in[7];
    const float* Wv   = (const float*)d_in[8];
    const float* bv   = (const float*)d_in[9];
    const float* Wo   = (const float*)d_in[10];
    const float* bo   = (const float*)d_in[11];
    float* out = (float*)d_out;

    float *qp, *kp, *vp, *at;
    cudaGetSymbolAddress((void**)&qp, g_qp);
    cudaGetSymbolAddress((void**)&kp, g_kp);
    cudaGetSymbolAddress((void**)&vp, g_vp);
    cudaGetSymbolAddress((void**)&at, g_at);

    const int SMEM_ATTN = (3 * 64 * TP + 4 * 64) * (int)sizeof(float);
    cudaFuncSetAttribute(attn_kernel,
                         cudaFuncAttributeMaxDynamicSharedMemorySize, SMEM_ATTN);

    dim3 gb(DD / 128, (BB * SS) / 128);   // (8, 32)
    gemm_bias_kernel<<<gb, 256>>>(q, Wq, bq, qp, BB * SS, DD, DD);
    gemm_bias_kernel<<<gb, 256>>>(k, Wk, bk, kp, BB * SS, DD, DD);
    gemm_bias_kernel<<<gb, 256>>>(v, Wv, bv, vp, BB * SS, DD, DD);

    attn_kernel<<<dim3(SS / 64, BB * HH), 256, SMEM_ATTN>>>(qp, kp, vp, mask, at);

    gemm_bias_kernel<<<gb, 256>>>(at, Wo, bo, out, BB * SS, DD, DD);
}

// round 4
// speedup vs baseline: 1.3512x; 1.3512x over previous
#include <cuda_runtime.h>
#include <cuda_bf16.h>
#include <math.h>
#include <cstdint>

#define BB 2
#define SS 2048
#define DD 1024
#define HH 16
#define DKK 64

// Scratch (allocation-free rule: __device__ globals)
__device__ float g_qp[BB * SS * DD];
__device__ float g_kp[BB * SS * DD];
__device__ float g_vp[BB * SS * DD];
__device__ float g_at[BB * SS * DD];

// ===========================================================================
// helpers
// ===========================================================================
__device__ __forceinline__ uint32_t smem_u32(const void* p) {
    uint32_t a;
    asm("{ .reg .u64 t; cvta.to.shared.u64 t, %1; cvt.u32.u64 %0, t; }"
        : "=r"(a) : "l"(p));
    return a;
}
__device__ __forceinline__ void ldm_x4(uint32_t* r, uint32_t addr) {
    asm volatile("ldmatrix.sync.aligned.m8n8.x4.shared.b16 {%0,%1,%2,%3}, [%4];"
                 : "=r"(r[0]), "=r"(r[1]), "=r"(r[2]), "=r"(r[3]) : "r"(addr));
}
__device__ __forceinline__ void ldm_x4t(uint32_t* r, uint32_t addr) {
    asm volatile("ldmatrix.sync.aligned.m8n8.x4.trans.shared.b16 {%0,%1,%2,%3}, [%4];"
                 : "=r"(r[0]), "=r"(r[1]), "=r"(r[2]), "=r"(r[3]) : "r"(addr));
}
__device__ __forceinline__ void mma16816(float* d, const uint32_t* a, const uint32_t* b) {
    asm volatile(
        "mma.sync.aligned.m16n8k16.row.col.f32.bf16.bf16.f32 "
        "{%0,%1,%2,%3}, {%4,%5,%6,%7}, {%8,%9}, {%0,%1,%2,%3};"
        : "+f"(d[0]), "+f"(d[1]), "+f"(d[2]), "+f"(d[3])
        : "r"(a[0]), "r"(a[1]), "r"(a[2]), "r"(a[3]), "r"(b[0]), "r"(b[1]));
}

// ===========================================================================
// bf16x3 split-precision tensor-core GEMM: C[M,N] = A[M,K] @ W[K,N] + bias
// Tile 128x128, BK=32. 8 warps, each 32m x 64n via m16n8k16 mma.sync.
// A smem [128][AP] row-major (k-contig); B smem [32][BP] (n-contig, ldmatrix.trans)
// ===========================================================================
#define AP 40    // A smem pitch in bf16 (80B = 5x16B banks -> conflict-free ldmatrix)
#define BP 136   // B smem pitch in bf16 (272B = 17x16B -> conflict-free ldmatrix)

__global__ __launch_bounds__(256, 2) void gemm_mma_kernel(
    const float* __restrict__ A, const float* __restrict__ W,
    const float* __restrict__ bias, float* __restrict__ C,
    int M, int N, int K)
{
    __shared__ __align__(16) uint16_t sAh[128 * AP];
    __shared__ __align__(16) uint16_t sAl[128 * AP];
    __shared__ __align__(16) uint16_t sBh[32 * BP];
    __shared__ __align__(16) uint16_t sBl[32 * BP];

    const int tid = threadIdx.x;
    const int wid = tid >> 5;
    const int lid = tid & 31;
    const int m0 = blockIdx.y * 128;
    const int n0 = blockIdx.x * 128;
    const int wm = (wid & 3) * 32;
    const int wn = (wid >> 2) * 64;

    const uint32_t aBaseH = smem_u32(sAh);
    const uint32_t aBaseL = smem_u32(sAl);
    const uint32_t bBaseH = smem_u32(sBh);
    const uint32_t bBaseL = smem_u32(sBl);

    // ldmatrix per-lane address components
    const int lrow = (lid & 7) + ((lid >> 3) & 1) * 8;  // 0..15
    const int lsel = (lid >> 4) * 8;                     // 0 or 8

    // global load assignment
    const int arow = tid >> 1;            // 0..127
    const int ahalf = (tid & 1) * 16;     // 0 or 16
    const int bk = tid >> 3;              // 0..31
    const int bnb = (tid & 7) * 16;       // 0..112

    const float* Aptr = A + (size_t)(m0 + arow) * K + ahalf;
    const float* Wptr = W + n0 + bnb;

    float acc[2][8][4];
#pragma unroll
    for (int i = 0; i < 2; i++)
#pragma unroll
        for (int j = 0; j < 8; j++)
#pragma unroll
            for (int r = 0; r < 4; r++) acc[i][j][r] = 0.f;

    for (int kb = 0; kb < K; kb += 32) {
        // ---- A tile -> hi/lo bf16 smem ----
#pragma unroll
        for (int j = 0; j < 4; j++) {
            float4 v = *(const float4*)(Aptr + kb + j * 4);
            __nv_bfloat162 h0 = __floats2bfloat162_rn(v.x, v.y);
            __nv_bfloat162 h1 = __floats2bfloat162_rn(v.z, v.w);
            __nv_bfloat162 l0 = __floats2bfloat162_rn(v.x - __bfloat162float(h0.x),
                                                      v.y - __bfloat162float(h0.y));
            __nv_bfloat162 l1 = __floats2bfloat162_rn(v.z - __bfloat162float(h1.x),
                                                      v.w - __bfloat162float(h1.y));
            int idx = arow * AP + ahalf + j * 4;
            *(uint32_t*)(sAh + idx)     = *(uint32_t*)&h0;
            *(uint32_t*)(sAh + idx + 2) = *(uint32_t*)&h1;
            *(uint32_t*)(sAl + idx)     = *(uint32_t*)&l0;
            *(uint32_t*)(sAl + idx + 2) = *(uint32_t*)&l1;
        }
        // ---- B tile (W[k][n], n-contiguous) -> hi/lo bf16 smem ----
#pragma unroll
        for (int j = 0; j < 4; j++) {
            float4 v = *(const float4*)(Wptr + (size_t)(kb + bk) * N + j * 4);
            __nv_bfloat162 h0 = __floats2bfloat162_rn(v.x, v.y);
            __nv_bfloat162 h1 = __floats2bfloat162_rn(v.z, v.w);
            __nv_bfloat162 l0 = __floats2bfloat162_rn(v.x - __bfloat162float(h0.x),
                                                      v.y - __bfloat162float(h0.y));
            __nv_bfloat162 l1 = __floats2bfloat162_rn(v.z - __bfloat162float(h1.x),
                                                      v.w - __bfloat162float(h1.y));
            int idx = bk * BP + bnb + j * 4;
            *(uint32_t*)(sBh + idx)     = *(uint32_t*)&h0;
            *(uint32_t*)(sBh + idx + 2) = *(uint32_t*)&h1;
            *(uint32_t*)(sBl + idx)     = *(uint32_t*)&l0;
            *(uint32_t*)(sBl + idx + 2) = *(uint32_t*)&l1;
        }
        __syncthreads();

#pragma unroll
        for (int ks = 0; ks < 2; ks++) {
            const int kk = ks * 16;
            uint32_t aH[2][4], aL[2][4];
#pragma unroll
            for (int mt = 0; mt < 2; mt++) {
                uint32_t off = (uint32_t)((wm + mt * 16 + lrow) * AP + kk + lsel) * 2;
                ldm_x4(aH[mt], aBaseH + off);
                ldm_x4(aL[mt], aBaseL + off);
            }
#pragma unroll
            for (int jp = 0; jp < 4; jp++) {
                uint32_t bH[4], bL[4];
                uint32_t boff = (uint32_t)((kk + lrow) * BP + wn + jp * 16 + lsel) * 2;
                ldm_x4t(bH, bBaseH + boff);
                ldm_x4t(bL, bBaseL + boff);
#pragma unroll
                for (int nt = 0; nt < 2; nt++) {
#pragma unroll
                    for (int mt = 0; mt < 2; mt++) {
                        float* d = acc[mt][jp * 2 + nt];
                        mma16816(d, aH[mt], bH + nt * 2);
                        mma16816(d, aH[mt], bL + nt * 2);
                        mma16816(d, aL[mt], bH + nt * 2);
                    }
                }
            }
        }
        __syncthreads();
    }

    // ---- epilogue: add bias, store fp32 ----
#pragma unroll
    for (int mt = 0; mt < 2; mt++) {
        const int row = m0 + wm + mt * 16 + (lid >> 2);
#pragma unroll
        for (int nt8 = 0; nt8 < 8; nt8++) {
            const int col = n0 + wn + nt8 * 8 + (lid & 3) * 2;
            float b0 = __ldg(bias + col);
            float b1 = __ldg(bias + col + 1);
            float2 s0 = make_float2(acc[mt][nt8][0] + b0, acc[mt][nt8][1] + b1);
            float2 s1 = make_float2(acc[mt][nt8][2] + b0, acc[mt][nt8][3] + b1);
            *(float2*)(C + (size_t)row * N + col)       = s0;
            *(float2*)(C + (size_t)(row + 8) * N + col) = s1;
        }
    }
}

// ---------------------------------------------------------------------------
// Flash attention (unchanged): one block = (b, h, 64-row q-tile).
// ---------------------------------------------------------------------------
#define TP 65  // smem row pitch

__global__ __launch_bounds__(256) void attn_kernel(
    const float* __restrict__ Qm, const float* __restrict__ Km,
    const float* __restrict__ Vm, const int* __restrict__ mask,
    float* __restrict__ Om)
{
    extern __shared__ float fsmem[];
    float* sQ  = fsmem;                 // 64*65
    float* sKV = sQ + 64 * TP;          // 64*65  (K, then reused for V)
    float* sS  = sKV + 64 * TP;         // 64*65
    float* sM  = sS + 64 * TP;          // 64
    float* sL  = sM + 64;               // 64
    float* sC  = sL + 64;               // 64
    float* sMk = sC + 64;               // 64

    const int tid = threadIdx.x;
    const int tx = tid & 15;
    const int ty = tid >> 4;
    const int b = blockIdx.y >> 4;
    const int h = blockIdx.y & 15;
    const int q0 = blockIdx.x << 6;

    const size_t headoff = (size_t)h * DKK;
    const float* Qb = Qm + ((size_t)b * SS + q0) * DD + headoff;
    const float* Kb = Km + (size_t)b * SS * DD + headoff;
    const float* Vb = Vm + (size_t)b * SS * DD + headoff;
    const int* mb = mask + b * SS;

#pragma unroll
    for (int p = 0; p < 4; p++) {
        int L = tid + p * 256;
        int r = L >> 4;
        int c = (L & 15) << 2;
        float4 v = *(const float4*)(Qb + (size_t)r * DD + c);
        sQ[r * TP + c + 0] = v.x * 0.125f;
        sQ[r * TP + c + 1] = v.y * 0.125f;
        sQ[r * TP + c + 2] = v.z * 0.125f;
        sQ[r * TP + c + 3] = v.w * 0.125f;
    }
    if (tid < 64) { sM[tid] = -3.0e38f; sL[tid] = 0.f; }

    float acc[4][4];
#pragma unroll
    for (int i = 0; i < 4; i++)
#pragma unroll
        for (int j = 0; j < 4; j++) acc[i][j] = 0.f;

    for (int kt = 0; kt < SS / 64; kt++) {
        const float* Kt = Kb + (size_t)kt * 64 * DD;
        const float* Vt = Vb + (size_t)kt * 64 * DD;

#pragma unroll
        for (int p = 0; p < 4; p++) {
            int L = tid + p * 256;
            int r = L >> 4;
            int c = (L & 15) << 2;
            float4 v = *(const float4*)(Kt + (size_t)r * DD + c);
            sKV[r * TP + c + 0] = v.x;
            sKV[r * TP + c + 1] = v.y;
            sKV[r * TP + c + 2] = v.z;
            sKV[r * TP + c + 3] = v.w;
        }
        if (tid < 64) sMk[tid] = (mb[kt * 64 + tid] != 0) ? 1.f : 0.f;
        __syncthreads();

        float s[4][4];
#pragma unroll
        for (int i = 0; i < 4; i++)
#pragma unroll
            for (int j = 0; j < 4; j++) s[i][j] = 0.f;
#pragma unroll
        for (int d = 0; d < 64; d++) {
            float qv[4], kv[4];
#pragma unroll
            for (int i = 0; i < 4; i++) qv[i] = sQ[(ty + 16 * i) * TP + d];
#pragma unroll
            for (int j = 0; j < 4; j++) kv[j] = sKV[(tx + 16 * j) * TP + d];
#pragma unroll
            for (int i = 0; i < 4; i++)
#pragma unroll
                for (int j = 0; j < 4; j++)
                    s[i][j] += qv[i] * kv[j];
        }
#pragma unroll
        for (int i = 0; i < 4; i++)
#pragma unroll
            for (int j = 0; j < 4; j++)
                sS[(ty + 16 * i) * TP + tx + 16 * j] = s[i][j];
        __syncthreads();

#pragma unroll
        for (int p = 0; p < 4; p++) {
            int L = tid + p * 256;
            int r = L >> 4;
            int c = (L & 15) << 2;
            float4 v = *(const float4*)(Vt + (size_t)r * DD + c);
            sKV[r * TP + c + 0] = v.x;
            sKV[r * TP + c + 1] = v.y;
            sKV[r * TP + c + 2] = v.z;
            sKV[r * TP + c + 3] = v.w;
        }

        if (tid < 64) {
            const int r = tid;
            float mOld = sM[r];
            float mt = mOld;
#pragma unroll 8
            for (int j = 0; j < 64; j++) {
                float sv = (sMk[j] != 0.f) ? -1.0e10f : sS[r * TP + j];
                sS[r * TP + j] = sv;
                mt = fmaxf(mt, sv);
            }
            float corr = __expf(mOld - mt);
            float l = sL[r] * corr;
#pragma unroll 8
            for (int j = 0; j < 64; j++) {
                float p = __expf(sS[r * TP + j] - mt);
                sS[r * TP + j] = p;
                l += p;
            }
            sL[r] = l;
            sM[r] = mt;
            sC[r] = corr;
        }
        __syncthreads();

        float cf[4];
#pragma unroll
        for (int i = 0; i < 4; i++) cf[i] = sC[ty + 16 * i];
#pragma unroll
        for (int i = 0; i < 4; i++)
#pragma unroll
            for (int j = 0; j < 4; j++) acc[i][j] *= cf[i];

#pragma unroll
        for (int k = 0; k < 64; k++) {
            float pv[4], vv[4];
#pragma unroll
            for (int i = 0; i < 4; i++) pv[i] = sS[(ty + 16 * i) * TP + k];
#pragma unroll
            for (int j = 0; j < 4; j++) vv[j] = sKV[k * TP + tx + 16 * j];
#pragma unroll
            for (int i = 0; i < 4; i++)
#pragma unroll
                for (int j = 0; j < 4; j++)
                    acc[i][j] += pv[i] * vv[j];
        }
        __syncthreads();
    }

#pragma unroll
    for (int i = 0; i < 4; i++) {
        int r = ty + 16 * i;
        float inv = 1.f / sL[r];
        float* Op = Om + ((size_t)b * SS + q0 + r) * DD + headoff;
#pragma unroll
        for (int j = 0; j < 4; j++)
            Op[tx + 16 * j] = acc[i][j] * inv;
    }
}

// ---------------------------------------------------------------------------
extern "C" void kernel_launch(void* const* d_in, const int* in_sizes, int n_in,
                              void* d_out, int out_size)
{
    const float* q    = (const float*)d_in[0];
    const float* k    = (const float*)d_in[1];
    const float* v    = (const float*)d_in[2];
    const int*   mask = (const int*)d_in[3];
    const float* Wq   = (const float*)d_in[4];
    const float* bq   = (const float*)d_in[5];
    const float* Wk   = (const float*)d_in[6];
    const float* bk   = (const float*)d_in[7];
    const float* Wv   = (const float*)d_in[8];
    const float* bv   = (const float*)d_in[9];
    const float* Wo   = (const float*)d_in[10];
    const float* bo   = (const float*)d_in[11];
    float* out = (float*)d_out;

    float *qp, *kp, *vp, *at;
    cudaGetSymbolAddress((void**)&qp, g_qp);
    cudaGetSymbolAddress((void**)&kp, g_kp);
    cudaGetSymbolAddress((void**)&vp, g_vp);
    cudaGetSymbolAddress((void**)&at, g_at);

    const int SMEM_ATTN = (3 * 64 * TP + 4 * 64) * (int)sizeof(float);
    cudaFuncSetAttribute(attn_kernel,
                         cudaFuncAttributeMaxDynamicSharedMemorySize, SMEM_ATTN);

    dim3 gb(DD / 128, (BB * SS) / 128);   // (8, 32)
    gemm_mma_kernel<<<gb, 256>>>(q, Wq, bq, qp, BB * SS, DD, DD);
    gemm_mma_kernel<<<gb, 256>>>(k, Wk, bk, kp, BB * SS, DD, DD);
    gemm_mma_kernel<<<gb, 256>>>(v, Wv, bv, vp, BB * SS, DD, DD);

    attn_kernel<<<dim3(SS / 64, BB * HH), 256, SMEM_ATTN>>>(qp, kp, vp, mask, at);

    gemm_mma_kernel<<<gb, 256>>>(at, Wo, bo, out, BB * SS, DD, DD);
}

// round 5
// speedup vs baseline: 2.8958x; 2.1431x over previous
#include <cuda_runtime.h>
#include <cuda_bf16.h>
#include <math.h>
#include <cstdint>

#define BB 2
#define SS 2048
#define DD 1024
#define HH 16
#define DKK 64

// Scratch (allocation-free rule: __device__ globals)
__device__ float g_qp[BB * SS * DD];
__device__ float g_kp[BB * SS * DD];
__device__ float g_vp[BB * SS * DD];
__device__ float g_at[BB * SS * DD];

// ===========================================================================
// helpers
// ===========================================================================
__device__ __forceinline__ uint32_t smem_u32(const void* p) {
    uint32_t a;
    asm("{ .reg .u64 t; cvta.to.shared.u64 t, %1; cvt.u32.u64 %0, t; }"
        : "=r"(a) : "l"(p));
    return a;
}
__device__ __forceinline__ void ldm_x4(uint32_t* r, uint32_t addr) {
    asm volatile("ldmatrix.sync.aligned.m8n8.x4.shared.b16 {%0,%1,%2,%3}, [%4];"
                 : "=r"(r[0]), "=r"(r[1]), "=r"(r[2]), "=r"(r[3]) : "r"(addr));
}
__device__ __forceinline__ void ldm_x4t(uint32_t* r, uint32_t addr) {
    asm volatile("ldmatrix.sync.aligned.m8n8.x4.trans.shared.b16 {%0,%1,%2,%3}, [%4];"
                 : "=r"(r[0]), "=r"(r[1]), "=r"(r[2]), "=r"(r[3]) : "r"(addr));
}
__device__ __forceinline__ void mma16816(float* d, const uint32_t* a, const uint32_t* b) {
    asm volatile(
        "mma.sync.aligned.m16n8k16.row.col.f32.bf16.bf16.f32 "
        "{%0,%1,%2,%3}, {%4,%5,%6,%7}, {%8,%9}, {%0,%1,%2,%3};"
        : "+f"(d[0]), "+f"(d[1]), "+f"(d[2]), "+f"(d[3])
        : "r"(a[0]), "r"(a[1]), "r"(a[2]), "r"(a[3]), "r"(b[0]), "r"(b[1]));
}
__device__ __forceinline__ uint32_t pack_bf16(float x, float y) {
    __nv_bfloat162 t = __floats2bfloat162_rn(x, y);
    return *(uint32_t*)&t;
}

// ===========================================================================
// bf16x3 split-precision tensor-core GEMM (unchanged from R4)
// ===========================================================================
#define AP 40
#define BP 136

__global__ __launch_bounds__(256, 2) void gemm_mma_kernel(
    const float* __restrict__ A, const float* __restrict__ W,
    const float* __restrict__ bias, float* __restrict__ C,
    int M, int N, int K)
{
    __shared__ __align__(16) uint16_t sAh[128 * AP];
    __shared__ __align__(16) uint16_t sAl[128 * AP];
    __shared__ __align__(16) uint16_t sBh[32 * BP];
    __shared__ __align__(16) uint16_t sBl[32 * BP];

    const int tid = threadIdx.x;
    const int wid = tid >> 5;
    const int lid = tid & 31;
    const int m0 = blockIdx.y * 128;
    const int n0 = blockIdx.x * 128;
    const int wm = (wid & 3) * 32;
    const int wn = (wid >> 2) * 64;

    const uint32_t aBaseH = smem_u32(sAh);
    const uint32_t aBaseL = smem_u32(sAl);
    const uint32_t bBaseH = smem_u32(sBh);
    const uint32_t bBaseL = smem_u32(sBl);

    const int lrow = (lid & 7) + ((lid >> 3) & 1) * 8;
    const int lsel = (lid >> 4) * 8;

    const int arow = tid >> 1;
    const int ahalf = (tid & 1) * 16;
    const int bk = tid >> 3;
    const int bnb = (tid & 7) * 16;

    const float* Aptr = A + (size_t)(m0 + arow) * K + ahalf;
    const float* Wptr = W + n0 + bnb;

    float acc[2][8][4];
#pragma unroll
    for (int i = 0; i < 2; i++)
#pragma unroll
        for (int j = 0; j < 8; j++)
#pragma unroll
            for (int r = 0; r < 4; r++) acc[i][j][r] = 0.f;

    for (int kb = 0; kb < K; kb += 32) {
#pragma unroll
        for (int j = 0; j < 4; j++) {
            float4 v = *(const float4*)(Aptr + kb + j * 4);
            __nv_bfloat162 h0 = __floats2bfloat162_rn(v.x, v.y);
            __nv_bfloat162 h1 = __floats2bfloat162_rn(v.z, v.w);
            __nv_bfloat162 l0 = __floats2bfloat162_rn(v.x - __bfloat162float(h0.x),
                                                      v.y - __bfloat162float(h0.y));
            __nv_bfloat162 l1 = __floats2bfloat162_rn(v.z - __bfloat162float(h1.x),
                                                      v.w - __bfloat162float(h1.y));
            int idx = arow * AP + ahalf + j * 4;
            *(uint32_t*)(sAh + idx)     = *(uint32_t*)&h0;
            *(uint32_t*)(sAh + idx + 2) = *(uint32_t*)&h1;
            *(uint32_t*)(sAl + idx)     = *(uint32_t*)&l0;
            *(uint32_t*)(sAl + idx + 2) = *(uint32_t*)&l1;
        }
#pragma unroll
        for (int j = 0; j < 4; j++) {
            float4 v = *(const float4*)(Wptr + (size_t)(kb + bk) * N + j * 4);
            __nv_bfloat162 h0 = __floats2bfloat162_rn(v.x, v.y);
            __nv_bfloat162 h1 = __floats2bfloat162_rn(v.z, v.w);
            __nv_bfloat162 l0 = __floats2bfloat162_rn(v.x - __bfloat162float(h0.x),
                                                      v.y - __bfloat162float(h0.y));
            __nv_bfloat162 l1 = __floats2bfloat162_rn(v.z - __bfloat162float(h1.x),
                                                      v.w - __bfloat162float(h1.y));
            int idx = bk * BP + bnb + j * 4;
            *(uint32_t*)(sBh + idx)     = *(uint32_t*)&h0;
            *(uint32_t*)(sBh + idx + 2) = *(uint32_t*)&h1;
            *(uint32_t*)(sBl + idx)     = *(uint32_t*)&l0;
            *(uint32_t*)(sBl + idx + 2) = *(uint32_t*)&l1;
        }
        __syncthreads();

#pragma unroll
        for (int ks = 0; ks < 2; ks++) {
            const int kk = ks * 16;
            uint32_t aH[2][4], aL[2][4];
#pragma unroll
            for (int mt = 0; mt < 2; mt++) {
                uint32_t off = (uint32_t)((wm + mt * 16 + lrow) * AP + kk + lsel) * 2;
                ldm_x4(aH[mt], aBaseH + off);
                ldm_x4(aL[mt], aBaseL + off);
            }
#pragma unroll
            for (int jp = 0; jp < 4; jp++) {
                uint32_t bH[4], bL[4];
                uint32_t boff = (uint32_t)((kk + lrow) * BP + wn + jp * 16 + lsel) * 2;
                ldm_x4t(bH, bBaseH + boff);
                ldm_x4t(bL, bBaseL + boff);
#pragma unroll
                for (int nt = 0; nt < 2; nt++) {
#pragma unroll
                    for (int mt = 0; mt < 2; mt++) {
                        float* d = acc[mt][jp * 2 + nt];
                        mma16816(d, aH[mt], bH + nt * 2);
                        mma16816(d, aH[mt], bL + nt * 2);
                        mma16816(d, aL[mt], bH + nt * 2);
                    }
                }
            }
        }
        __syncthreads();
    }

#pragma unroll
    for (int mt = 0; mt < 2; mt++) {
        const int row = m0 + wm + mt * 16 + (lid >> 2);
#pragma unroll
        for (int nt8 = 0; nt8 < 8; nt8++) {
            const int col = n0 + wn + nt8 * 8 + (lid & 3) * 2;
            float b0 = __ldg(bias + col);
            float b1 = __ldg(bias + col + 1);
            float2 s0 = make_float2(acc[mt][nt8][0] + b0, acc[mt][nt8][1] + b1);
            float2 s1 = make_float2(acc[mt][nt8][2] + b0, acc[mt][nt8][3] + b1);
            *(float2*)(C + (size_t)row * N + col)       = s0;
            *(float2*)(C + (size_t)(row + 8) * N + col) = s1;
        }
    }
}

// ===========================================================================
// Tensor-core flash attention, bf16x3 split both GEMMs.
// Block = (b, h, 128 q-rows). 8 warps; warp w owns q-rows [w*16, w*16+16).
// Softmax entirely warp-local (row spans one warp). KV tiles of 64.
// ===========================================================================
#define QP 72   // Q smem pitch (bf16) — 144B rows, ldmatrix conflict-free
#define KVP 72  // KV smem pitch

// dynamic smem layout (bytes)
#define AT_QH 0
#define AT_QL (AT_QH + 128 * QP * 2)       // 18432
#define AT_KVH (AT_QL + 128 * QP * 2)      // 36864
#define AT_KVL (AT_KVH + 64 * KVP * 2)     // 46080
#define AT_MK (AT_KVL + 64 * KVP * 2)      // 55296
#define AT_SMEM (AT_MK + 64 * 4)           // 55552

__global__ __launch_bounds__(256, 2) void attn_mma_kernel(
    const float* __restrict__ Qm, const float* __restrict__ Km,
    const float* __restrict__ Vm, const int* __restrict__ mask,
    float* __restrict__ Om)
{
    extern __shared__ char smem[];
    uint16_t* sQh = (uint16_t*)(smem + AT_QH);
    uint16_t* sQl = (uint16_t*)(smem + AT_QL);
    uint16_t* sKVh = (uint16_t*)(smem + AT_KVH);
    uint16_t* sKVl = (uint16_t*)(smem + AT_KVL);
    float* sMk = (float*)(smem + AT_MK);

    const uint32_t qhB = smem_u32(sQh);
    const uint32_t qlB = smem_u32(sQl);
    const uint32_t kvhB = smem_u32(sKVh);
    const uint32_t kvlB = smem_u32(sKVl);

    const int tid = threadIdx.x;
    const int wid = tid >> 5;
    const int lid = tid & 31;
    const int b = blockIdx.y >> 4;
    const int h = blockIdx.y & 15;
    const int q0 = blockIdx.x << 7;      // 128-row q tile

    const int lrow = (lid & 7) + ((lid >> 3) & 1) * 8;
    const int lsel = (lid >> 4) * 8;
    const int qr = lid >> 2;             // quad row 0..7
    const int qc = (lid & 3) * 2;        // quad col pair base

    const size_t headoff = (size_t)h * DKK;
    const int* mb = mask + b * SS;

    // ---- load Q tile 128x64, scale, split hi/lo ----
    {
        const float* Qb = Qm + ((size_t)b * SS + q0) * DD + headoff;
#pragma unroll
        for (int p = 0; p < 8; p++) {
            int idx = tid + p * 256;         // 0..2047
            int r = idx >> 4;
            int c = (idx & 15) << 2;
            float4 v = *(const float4*)(Qb + (size_t)r * DD + c);
            v.x *= 0.125f; v.y *= 0.125f; v.z *= 0.125f; v.w *= 0.125f;
            __nv_bfloat162 h0 = __floats2bfloat162_rn(v.x, v.y);
            __nv_bfloat162 h1 = __floats2bfloat162_rn(v.z, v.w);
            __nv_bfloat162 l0 = __floats2bfloat162_rn(v.x - __bfloat162float(h0.x),
                                                      v.y - __bfloat162float(h0.y));
            __nv_bfloat162 l1 = __floats2bfloat162_rn(v.z - __bfloat162float(h1.x),
                                                      v.w - __bfloat162float(h1.y));
            int sidx = r * QP + c;
            *(uint32_t*)(sQh + sidx)     = *(uint32_t*)&h0;
            *(uint32_t*)(sQh + sidx + 2) = *(uint32_t*)&h1;
            *(uint32_t*)(sQl + sidx)     = *(uint32_t*)&l0;
            *(uint32_t*)(sQl + sidx + 2) = *(uint32_t*)&l1;
        }
    }

    float o[8][4];
#pragma unroll
    for (int j = 0; j < 8; j++)
#pragma unroll
        for (int r = 0; r < 4; r++) o[j][r] = 0.f;
    float m0v = -3.0e38f, m1v = -3.0e38f, l0v = 0.f, l1v = 0.f;

    for (int kt = 0; kt < SS / 64; kt++) {
        const int kv0 = kt * 64;
        __syncthreads();   // prior V reads done; Q store done (first iter)

        // ---- load K tile 64x64 -> hi/lo ----
        {
            const float* Kb = Km + ((size_t)b * SS + kv0) * DD + headoff;
#pragma unroll
            for (int p = 0; p < 4; p++) {
                int idx = tid + p * 256;
                int r = idx >> 4;
                int c = (idx & 15) << 2;
                float4 v = *(const float4*)(Kb + (size_t)r * DD + c);
                __nv_bfloat162 h0 = __floats2bfloat162_rn(v.x, v.y);
                __nv_bfloat162 h1 = __floats2bfloat162_rn(v.z, v.w);
                __nv_bfloat162 l0 = __floats2bfloat162_rn(v.x - __bfloat162float(h0.x),
                                                          v.y - __bfloat162float(h0.y));
                __nv_bfloat162 l1 = __floats2bfloat162_rn(v.z - __bfloat162float(h1.x),
                                                          v.w - __bfloat162float(h1.y));
                int sidx = r * KVP + c;
                *(uint32_t*)(sKVh + sidx)     = *(uint32_t*)&h0;
                *(uint32_t*)(sKVh + sidx + 2) = *(uint32_t*)&h1;
                *(uint32_t*)(sKVl + sidx)     = *(uint32_t*)&l0;
                *(uint32_t*)(sKVl + sidx + 2) = *(uint32_t*)&l1;
            }
            if (tid < 64) sMk[tid] = (mb[kv0 + tid] != 0) ? -1.0e10f : 0.f;
        }
        __syncthreads();

        // ---- S = Q @ K^T (bf16x3) ----
        float s[8][4];
#pragma unroll
        for (int j = 0; j < 8; j++)
#pragma unroll
            for (int r = 0; r < 4; r++) s[j][r] = 0.f;

#pragma unroll
        for (int k = 0; k < 4; k++) {
            uint32_t qh[4], ql[4];
            uint32_t qoff = (uint32_t)((wid * 16 + lrow) * QP + k * 16 + lsel) * 2;
            ldm_x4(qh, qhB + qoff);
            ldm_x4(ql, qlB + qoff);
#pragma unroll
            for (int nb = 0; nb < 4; nb++) {
                uint32_t kh[4], kl[4];
                uint32_t koff = (uint32_t)((nb * 16 + lrow) * KVP + k * 16 + lsel) * 2;
                ldm_x4(kh, kvhB + koff);
                ldm_x4(kl, kvlB + koff);
                uint32_t bh0[2] = {kh[0], kh[2]}, bh1[2] = {kh[1], kh[3]};
                uint32_t bl0[2] = {kl[0], kl[2]}, bl1[2] = {kl[1], kl[3]};
                mma16816(s[nb * 2], qh, bh0);
                mma16816(s[nb * 2], qh, bl0);
                mma16816(s[nb * 2], ql, bh0);
                mma16816(s[nb * 2 + 1], qh, bh1);
                mma16816(s[nb * 2 + 1], qh, bl1);
                mma16816(s[nb * 2 + 1], ql, bh1);
            }
        }

        // ---- additive mask ----
#pragma unroll
        for (int j = 0; j < 8; j++) {
            float2 mk = *(float2*)&sMk[j * 8 + qc];
            s[j][0] += mk.x; s[j][1] += mk.y;
            s[j][2] += mk.x; s[j][3] += mk.y;
        }
        __syncthreads();   // K reads done

        // ---- load V tile into same buffers ----
        {
            const float* Vb = Vm + ((size_t)b * SS + kv0) * DD + headoff;
#pragma unroll
            for (int p = 0; p < 4; p++) {
                int idx = tid + p * 256;
                int r = idx >> 4;
                int c = (idx & 15) << 2;
                float4 v = *(const float4*)(Vb + (size_t)r * DD + c);
                __nv_bfloat162 h0 = __floats2bfloat162_rn(v.x, v.y);
                __nv_bfloat162 h1 = __floats2bfloat162_rn(v.z, v.w);
                __nv_bfloat162 l0 = __floats2bfloat162_rn(v.x - __bfloat162float(h0.x),
                                                          v.y - __bfloat162float(h0.y));
                __nv_bfloat162 l1 = __floats2bfloat162_rn(v.z - __bfloat162float(h1.x),
                                                          v.w - __bfloat162float(h1.y));
                int sidx = r * KVP + c;
                *(uint32_t*)(sKVh + sidx)     = *(uint32_t*)&h0;
                *(uint32_t*)(sKVh + sidx + 2) = *(uint32_t*)&h1;
                *(uint32_t*)(sKVl + sidx)     = *(uint32_t*)&l0;
                *(uint32_t*)(sKVl + sidx + 2) = *(uint32_t*)&l1;
            }
        }

        // ---- warp-local online softmax (registers) ----
        float mt0 = -3.0e38f, mt1 = -3.0e38f;
#pragma unroll
        for (int j = 0; j < 8; j++) {
            mt0 = fmaxf(mt0, fmaxf(s[j][0], s[j][1]));
            mt1 = fmaxf(mt1, fmaxf(s[j][2], s[j][3]));
        }
        mt0 = fmaxf(mt0, __shfl_xor_sync(0xFFFFFFFF, mt0, 1));
        mt0 = fmaxf(mt0, __shfl_xor_sync(0xFFFFFFFF, mt0, 2));
        mt1 = fmaxf(mt1, __shfl_xor_sync(0xFFFFFFFF, mt1, 1));
        mt1 = fmaxf(mt1, __shfl_xor_sync(0xFFFFFFFF, mt1, 2));

        float mn0 = fmaxf(m0v, mt0), mn1 = fmaxf(m1v, mt1);
        float corr0 = __expf(m0v - mn0), corr1 = __expf(m1v - mn1);
        m0v = mn0; m1v = mn1;

        float ts0 = 0.f, ts1 = 0.f;
#pragma unroll
        for (int j = 0; j < 8; j++) {
            s[j][0] = __expf(s[j][0] - mn0);
            s[j][1] = __expf(s[j][1] - mn0);
            s[j][2] = __expf(s[j][2] - mn1);
            s[j][3] = __expf(s[j][3] - mn1);
            ts0 += s[j][0] + s[j][1];
            ts1 += s[j][2] + s[j][3];
        }
        ts0 += __shfl_xor_sync(0xFFFFFFFF, ts0, 1);
        ts0 += __shfl_xor_sync(0xFFFFFFFF, ts0, 2);
        ts1 += __shfl_xor_sync(0xFFFFFFFF, ts1, 1);
        ts1 += __shfl_xor_sync(0xFFFFFFFF, ts1, 2);
        l0v = l0v * corr0 + ts0;
        l1v = l1v * corr1 + ts1;

#pragma unroll
        for (int j = 0; j < 8; j++) {
            o[j][0] *= corr0; o[j][1] *= corr0;
            o[j][2] *= corr1; o[j][3] *= corr1;
        }
        __syncthreads();   // V ready

        // ---- O += P @ V (bf16x3), P packed per k-step on the fly ----
#pragma unroll
        for (int t = 0; t < 4; t++) {
            uint32_t pah[4], pal[4];
            {
                float p00 = s[2 * t][0],     p01 = s[2 * t][1];
                float p10 = s[2 * t][2],     p11 = s[2 * t][3];
                float p20 = s[2 * t + 1][0], p21 = s[2 * t + 1][1];
                float p30 = s[2 * t + 1][2], p31 = s[2 * t + 1][3];
                pah[0] = pack_bf16(p00, p01);
                pah[1] = pack_bf16(p10, p11);
                pah[2] = pack_bf16(p20, p21);
                pah[3] = pack_bf16(p30, p31);
                __nv_bfloat162* hb;
                hb = (__nv_bfloat162*)&pah[0];
                pal[0] = pack_bf16(p00 - __bfloat162float(hb->x), p01 - __bfloat162float(hb->y));
                hb = (__nv_bfloat162*)&pah[1];
                pal[1] = pack_bf16(p10 - __bfloat162float(hb->x), p11 - __bfloat162float(hb->y));
                hb = (__nv_bfloat162*)&pah[2];
                pal[2] = pack_bf16(p20 - __bfloat162float(hb->x), p21 - __bfloat162float(hb->y));
                hb = (__nv_bfloat162*)&pah[3];
                pal[3] = pack_bf16(p30 - __bfloat162float(hb->x), p31 - __bfloat162float(hb->y));
            }
#pragma unroll
            for (int nb = 0; nb < 4; nb++) {
                uint32_t vh[4], vl[4];
                uint32_t voff = (uint32_t)((t * 16 + lrow) * KVP + nb * 16 + lsel) * 2;
                ldm_x4t(vh, kvhB + voff);
                ldm_x4t(vl, kvlB + voff);
                mma16816(o[nb * 2], pah, vh);
                mma16816(o[nb * 2], pah, vl);
                mma16816(o[nb * 2], pal, vh);
                mma16816(o[nb * 2 + 1], pah, vh + 2);
                mma16816(o[nb * 2 + 1], pah, vl + 2);
                mma16816(o[nb * 2 + 1], pal, vh + 2);
            }
        }
    }

    // ---- epilogue ----
    float inv0 = 1.f / l0v, inv1 = 1.f / l1v;
    const int r0g = q0 + wid * 16 + qr;
#pragma unroll
    for (int j = 0; j < 8; j++) {
        const size_t col = headoff + j * 8 + qc;
        float2 v0 = make_float2(o[j][0] * inv0, o[j][1] * inv0);
        float2 v1 = make_float2(o[j][2] * inv1, o[j][3] * inv1);
        *(float2*)(Om + ((size_t)b * SS + r0g) * DD + col)     = v0;
        *(float2*)(Om + ((size_t)b * SS + r0g + 8) * DD + col) = v1;
    }
}

// ---------------------------------------------------------------------------
extern "C" void kernel_launch(void* const* d_in, const int* in_sizes, int n_in,
                              void* d_out, int out_size)
{
    const float* q    = (const float*)d_in[0];
    const float* k    = (const float*)d_in[1];
    const float* v    = (const float*)d_in[2];
    const int*   mask = (const int*)d_in[3];
    const float* Wq   = (const float*)d_in[4];
    const float* bq   = (const float*)d_in[5];
    const float* Wk   = (const float*)d_in[6];
    const float* bk   = (const float*)d_in[7];
    const float* Wv   = (const float*)d_in[8];
    const float* bv   = (const float*)d_in[9];
    const float* Wo   = (const float*)d_in[10];
    const float* bo   = (const float*)d_in[11];
    float* out = (float*)d_out;

    float *qp, *kp, *vp, *at;
    cudaGetSymbolAddress((void**)&qp, g_qp);
    cudaGetSymbolAddress((void**)&kp, g_kp);
    cudaGetSymbolAddress((void**)&vp, g_vp);
    cudaGetSymbolAddress((void**)&at, g_at);

    cudaFuncSetAttribute(attn_mma_kernel,
                         cudaFuncAttributeMaxDynamicSharedMemorySize, AT_SMEM);

    dim3 gb(DD / 128, (BB * SS) / 128);   // (8, 32)
    gemm_mma_kernel<<<gb, 256>>>(q, Wq, bq, qp, BB * SS, DD, DD);
    gemm_mma_kernel<<<gb, 256>>>(k, Wk, bk, kp, BB * SS, DD, DD);
    gemm_mma_kernel<<<gb, 256>>>(v, Wv, bv, vp, BB * SS, DD, DD);

    attn_mma_kernel<<<dim3(SS / 128, BB * HH), 256, AT_SMEM>>>(qp, kp, vp, mask, at);

    gemm_mma_kernel<<<gb, 256>>>(at, Wo, bo, out, BB * SS, DD, DD);
}